// round 5
// baseline (speedup 1.0000x reference)
#include <cuda_runtime.h>
#include <cuda_bf16.h>
#include <math.h>

#define BATCH 2048
#define IN_C  256
#define OUT_C 256
#define NSPL  5
#define NINT  16

// params: float4 = {b3*log2e, b4, b2*ln2, b1*g*ln2}, scalar = b5*g, layout [i][o]
__device__ float4 g_par4[IN_C * OUT_C];
__device__ float  g_par1[IN_C * OUT_C];
// per-batch compacted active list: (x, i*256 as int bits), padded to multiple of 4
__device__ float2 g_act[BATCH * IN_C];
__device__ int    g_cnt[BATCH];

__device__ __forceinline__ float ex2f(float x) {
    float r; asm("ex2.approx.f32 %0, %1;" : "=f"(r) : "f"(x)); return r;
}
__device__ __forceinline__ float lg2f(float x) {
    float r; asm("lg2.approx.f32 %0, %1;" : "=f"(r) : "f"(x)); return r;
}

// FMA-pipe exp2 for t in [0, ~16): magic-number split + degree-6 Taylor/minimax.
// Offloads the MUFU pipe (the binding resource); abs rel err ~3e-8.
__device__ __forceinline__ float ex2_poly(float t) {
    const float MAGIC = 12582912.0f;  // 1.5 * 2^23
    float k = t + MAGIC;
    int   e = __float_as_int(k) << 23;      // integer part -> exponent field
    float f = t - (k - MAGIC);              // f in [-0.5, 0.5]
    float r = 1.54035304e-4f;
    r = fmaf(r, f, 1.33335581e-3f);
    r = fmaf(r, f, 9.61812911e-3f);
    r = fmaf(r, f, 5.55041087e-2f);
    r = fmaf(r, f, 2.40226507e-1f);
    r = fmaf(r, f, 6.93147181e-1f);
    r = fmaf(r, f, 1.0f);
    return __int_as_float(__float_as_int(r) + e);
}

// Merged pre-pass: blocks [0,256) compute spline params; blocks [256,512) compact x.
__global__ void __launch_bounds__(256)
kan_pre(const float* __restrict__ x,
        const float* __restrict__ w,
        const float* __restrict__ raw_gamma,
        const float* __restrict__ breaks,
        const float* __restrict__ coefs,
        const float* __restrict__ mu_p,
        const float* __restrict__ sigma_p) {
    if (blockIdx.x < 256) {
        __shared__ float brk_s[NSPL][NINT + 1];
        __shared__ float cf_s[NSPL * NINT * 4];
        int tid = threadIdx.x;
        for (int j = tid; j < NSPL * (NINT + 1); j += 256)
            brk_s[j / (NINT + 1)][j % (NINT + 1)] = breaks[j];
        for (int j = tid; j < NSPL * NINT * 4; j += 256)
            cf_s[j] = coefs[j];
        __syncthreads();

        int idx = blockIdx.x * 256 + tid;
        int i = idx >> 8;
        int o = idx & 255;
        int widx = o * IN_C + i;   // w is [OUT][IN]

        float mu = *mu_p, sigma = *sigma_p;
        float wv = w[widx];
        wv = fminf(fmaxf(wv, 5.5f), 35.5f);
        float wn = (wv - mu) / sigma;

        float b[NSPL];
#pragma unroll
        for (int s = 0; s < NSPL; s++) {
            float lo = brk_s[s][0];
            float hib = brk_s[s][NINT] - 1e-6f;
            float wc = fminf(fmaxf(wn, lo), hib);
            int k = 0;
#pragma unroll
            for (int kk = 1; kk <= NINT; kk++) k += (brk_s[s][kk] <= wc) ? 1 : 0;
            if (k > NINT - 1) k = NINT - 1;
            float t = wc - brk_s[s][k];
            const float* a = &cf_s[(s * NINT + k) * 4];
            b[s] = ((a[0] * t + a[1]) * t + a[2]) * t + a[3];
        }

        float rg = raw_gamma[widx];
        float g = fmaxf(rg, 0.0f) + log1pf(expf(-fabsf(rg)));
        g *= (1.0f / (float)OUT_C);

        const float LN2 = 0.69314718055994530942f;
        const float L2E = 1.44269504088896340736f;
        g_par4[idx] = make_float4(b[2] * L2E, b[3], b[1] * LN2, b[0] * g * LN2);
        g_par1[idx] = b[4] * g;
    } else {
        int wrp = threadIdx.x >> 5, lane = threadIdx.x & 31;
        int b = (blockIdx.x - 256) * 8 + wrp;
        const float* xb = x + b * IN_C;
        int cnt = 0;
#pragma unroll
        for (int h = 0; h < IN_C / 32; h++) {
            int il = h * 32 + lane;
            float xv = xb[il];
            bool act = xv > 0.0f;
            unsigned m = __ballot_sync(0xffffffffu, act);
            int pos = __popc(m & ((1u << lane) - 1));
            if (act) g_act[b * IN_C + cnt + pos] =
                         make_float2(xv, __int_as_float(il << 8));
            cnt += __popc(m);
        }
        int padded = (cnt + 3) & ~3;
        if (lane < padded - cnt)
            g_act[b * IN_C + cnt + lane] = make_float2(0.0f, __int_as_float(0));
        if (lane == 0) g_cnt[b] = padded;
    }
}

__global__ void __launch_bounds__(256)
kan_main(float* __restrict__ out) {
    int tid  = threadIdx.x;
    int lane = tid & 31;
    int wrp  = tid >> 5;
    int b    = blockIdx.x * 8 + wrp;         // one batch per warp
    int o    = blockIdx.y * 32 + lane;       // one output per lane

    const float4* __restrict__ p4 = g_par4 + o;
    const float*  __restrict__ p1 = g_par1 + o;
    const float4* __restrict__ ap = (const float4*)(g_act + b * IN_C);

    int cnt = g_cnt[b];
    float acc0 = 0.0f, acc1 = 0.0f, acc2 = 0.0f, acc3 = 0.0f;

    for (int n = 0; n < cnt; n += 4) {
        float4 e01 = __ldg(&ap[n >> 1]);
        float4 e23 = __ldg(&ap[(n >> 1) + 1]);
        float xs[4] = {e01.x, e01.z, e23.x, e23.z};
        int   is[4] = {__float_as_int(e01.y), __float_as_int(e01.w),
                       __float_as_int(e23.y), __float_as_int(e23.w)};
        float4 P[4];
        float  c5[4];
#pragma unroll
        for (int q = 0; q < 4; q++) {
            P[q]  = __ldg(p4 + is[q]);
            c5[q] = __ldg(p1 + is[q]);
        }
        float r[4];
#pragma unroll
        for (int q = 0; q < 4; q++) {
            float xv   = xs[q];
            float e    = ex2_poly(P[q].x * xv);           // exp(b3*x) on FMA pipe
            float base = fmaxf(e - 1.0f, 0.0f);
            float pw   = ex2f(P[q].y * lg2f(base));       // base^b4 (0 -> 0)
            float lgA  = lg2f(pw + 1.0f);
            float lgB  = lg2f(fmaf(P[q].z, lgA, 1.0f));
            r[q] = fmaf(P[q].w, lgB, c5[q] * xv);
        }
        acc0 += r[0]; acc1 += r[1]; acc2 += r[2]; acc3 += r[3];
    }

    float y  = (acc0 + acc1) + (acc2 + acc3);
    float sp = fmaxf(y, 0.0f) + log1pf(expf(-fabsf(y)));
    out[b * OUT_C + o] = sp;
}

extern "C" void kernel_launch(void* const* d_in, const int* in_sizes, int n_in,
                              void* d_out, int out_size) {
    const float* x         = (const float*)d_in[0];
    const float* w         = (const float*)d_in[1];
    const float* raw_gamma = (const float*)d_in[2];
    const float* breaks    = (const float*)d_in[3];
    const float* coefs     = (const float*)d_in[4];
    const float* mu        = (const float*)d_in[5];
    const float* sigma     = (const float*)d_in[6];
    float* out = (float*)d_out;

    kan_pre<<<512, 256>>>(x, w, raw_gamma, breaks, coefs, mu, sigma);

    dim3 grid(BATCH / 8, OUT_C / 32);
    kan_main<<<grid, 256>>>(out);
}

// round 6
// speedup vs baseline: 1.0393x; 1.0393x over previous
#include <cuda_runtime.h>
#include <cuda_bf16.h>
#include <math.h>

#define BATCH 2048
#define IN_C  256
#define OUT_C 256
#define NSPL  5
#define NINT  16

// params: float4 = {b3*log2e, b4, b2*ln2, b1*g*ln2}, scalar = b5*g, layout [i][o]
__device__ float4 g_par4[IN_C * OUT_C];
__device__ float  g_par1[IN_C * OUT_C];
// per-batch compacted active list: (x, i*256 as int bits), padded to multiple of 8
__device__ float2 g_act[BATCH * IN_C];
__device__ int    g_cnt[BATCH];

__device__ __forceinline__ float ex2f(float x) {
    float r; asm("ex2.approx.f32 %0, %1;" : "=f"(r) : "f"(x)); return r;
}
__device__ __forceinline__ float lg2f(float x) {
    float r; asm("lg2.approx.f32 %0, %1;" : "=f"(r) : "f"(x)); return r;
}

// Merged pre-pass: blocks [0,256) compute spline params; blocks [256,512) compact x.
__global__ void __launch_bounds__(256)
kan_pre(const float* __restrict__ x,
        const float* __restrict__ w,
        const float* __restrict__ raw_gamma,
        const float* __restrict__ breaks,
        const float* __restrict__ coefs,
        const float* __restrict__ mu_p,
        const float* __restrict__ sigma_p) {
    if (blockIdx.x < 256) {
        __shared__ float brk_s[NSPL][NINT + 1];
        __shared__ float cf_s[NSPL * NINT * 4];
        int tid = threadIdx.x;
        for (int j = tid; j < NSPL * (NINT + 1); j += 256)
            brk_s[j / (NINT + 1)][j % (NINT + 1)] = breaks[j];
        for (int j = tid; j < NSPL * NINT * 4; j += 256)
            cf_s[j] = coefs[j];
        __syncthreads();

        int idx = blockIdx.x * 256 + tid;
        int i = idx >> 8;
        int o = idx & 255;
        int widx = o * IN_C + i;   // w is [OUT][IN]

        float mu = *mu_p, sigma = *sigma_p;
        float wv = w[widx];
        wv = fminf(fmaxf(wv, 5.5f), 35.5f);
        float wn = (wv - mu) / sigma;

        float b[NSPL];
#pragma unroll
        for (int s = 0; s < NSPL; s++) {
            float lo = brk_s[s][0];
            float hib = brk_s[s][NINT] - 1e-6f;
            float wc = fminf(fmaxf(wn, lo), hib);
            int k = 0;
#pragma unroll
            for (int kk = 1; kk <= NINT; kk++) k += (brk_s[s][kk] <= wc) ? 1 : 0;
            if (k > NINT - 1) k = NINT - 1;
            float t = wc - brk_s[s][k];
            const float* a = &cf_s[(s * NINT + k) * 4];
            b[s] = ((a[0] * t + a[1]) * t + a[2]) * t + a[3];
        }

        float rg = raw_gamma[widx];
        float g = fmaxf(rg, 0.0f) + log1pf(expf(-fabsf(rg)));
        g *= (1.0f / (float)OUT_C);

        const float LN2 = 0.69314718055994530942f;
        const float L2E = 1.44269504088896340736f;
        g_par4[idx] = make_float4(b[2] * L2E, b[3], b[1] * LN2, b[0] * g * LN2);
        g_par1[idx] = b[4] * g;
    } else {
        int wrp = threadIdx.x >> 5, lane = threadIdx.x & 31;
        int b = (blockIdx.x - 256) * 8 + wrp;
        const float* xb = x + b * IN_C;
        int cnt = 0;
#pragma unroll
        for (int h = 0; h < IN_C / 32; h++) {
            int il = h * 32 + lane;
            float xv = xb[il];
            bool act = xv > 0.0f;
            unsigned m = __ballot_sync(0xffffffffu, act);
            int pos = __popc(m & ((1u << lane) - 1));
            if (act) g_act[b * IN_C + cnt + pos] =
                         make_float2(xv, __int_as_float(il << 8));
            cnt += __popc(m);
        }
        int padded = (cnt + 7) & ~7;           // pad to 8 for unrolled main loop
        if (lane < padded - cnt)
            g_act[b * IN_C + cnt + lane] = make_float2(0.0f, __int_as_float(0));
        if (lane == 0) g_cnt[b] = padded;
    }
}

// One transcendental chain; zero-x (padding) contributes exactly 0.
#define CHAIN(XV, IV, A, B) do {                                   \
    int   _i  = __float_as_int(IV);                                \
    float4 _P = __ldg(p4 + _i);                                    \
    float _c5 = __ldg(p1 + _i);                                    \
    float _e  = ex2f(_P.x * (XV));                                 \
    float _bs = fmaxf(_e - 1.0f, 0.0f);                            \
    float _pw = ex2f(_P.y * lg2f(_bs));                            \
    float _lA = lg2f(_pw + 1.0f);                                  \
    float _lB = lg2f(fmaf(_P.z, _lA, 1.0f));                       \
    (A) = fmaf(_P.w, _lB, (A));                                    \
    (B) = fmaf(_c5, (XV), (B));                                    \
} while (0)

__global__ void __launch_bounds__(256)
kan_main(float* __restrict__ out) {
    int lane = threadIdx.x & 31;
    int wrp  = threadIdx.x >> 5;
    int b    = blockIdx.x * 8 + wrp;         // one batch per warp
    int o    = blockIdx.y * 32 + lane;       // one output per lane

    const float4* __restrict__ p4 = g_par4 + o;
    const float*  __restrict__ p1 = g_par1 + o;
    const float4* __restrict__ ap = (const float4*)(g_act + b * IN_C);

    int cnt = g_cnt[b];                      // multiple of 8
    float A0 = 0.f, A1 = 0.f, A2 = 0.f, A3 = 0.f;
    float B0 = 0.f, B1 = 0.f, B2 = 0.f, B3 = 0.f;

    for (int n = 0; n < cnt; n += 8) {
        int h = n >> 1;
        float4 e01 = __ldg(ap + h);
        float4 e23 = __ldg(ap + h + 1);
        float4 e45 = __ldg(ap + h + 2);
        float4 e67 = __ldg(ap + h + 3);
        CHAIN(e01.x, e01.y, A0, B0);
        CHAIN(e01.z, e01.w, A1, B1);
        CHAIN(e23.x, e23.y, A2, B2);
        CHAIN(e23.z, e23.w, A3, B3);
        CHAIN(e45.x, e45.y, A0, B0);
        CHAIN(e45.z, e45.w, A1, B1);
        CHAIN(e67.x, e67.y, A2, B2);
        CHAIN(e67.z, e67.w, A3, B3);
    }

    float y  = ((A0 + A1) + (A2 + A3)) + ((B0 + B1) + (B2 + B3));
    float sp = fmaxf(y, 0.0f) + log1pf(expf(-fabsf(y)));
    out[b * OUT_C + o] = sp;
}

extern "C" void kernel_launch(void* const* d_in, const int* in_sizes, int n_in,
                              void* d_out, int out_size) {
    const float* x         = (const float*)d_in[0];
    const float* w         = (const float*)d_in[1];
    const float* raw_gamma = (const float*)d_in[2];
    const float* breaks    = (const float*)d_in[3];
    const float* coefs     = (const float*)d_in[4];
    const float* mu        = (const float*)d_in[5];
    const float* sigma     = (const float*)d_in[6];
    float* out = (float*)d_out;

    kan_pre<<<512, 256>>>(x, w, raw_gamma, breaks, coefs, mu, sigma);

    dim3 grid(BATCH / 8, OUT_C / 32);
    kan_main<<<grid, 256>>>(out);
}